// round 8
// baseline (speedup 1.0000x reference)
#include <cuda_runtime.h>

#define BSZ 64
#define NSEQ 4096
#define DM 64
#define NSL 7
#define HH 128
#define CH 16          // chunks of N per batch for attention
#define LN_EPS 1e-5f
#define ATT_EPS 1e-8f

// ---------------- scratch (static device allocations are the sanctioned path) ----
__device__ float g_K[BSZ * NSEQ * DM];            // 67 MB
__device__ float g_V[BSZ * NSEQ * DM];            // 67 MB
__device__ float g_Q[BSZ * NSL * DM];
__device__ float g_slots[BSZ * NSL * DM];
__device__ float g_Up[BSZ * CH * NSL * DM];
__device__ float g_Sp[BSZ * CH * NSL];

// ---------------- packed f32x2 helpers (sm_103a FFMA2 path) ---------------------
__device__ __forceinline__ unsigned long long pk2(float lo, float hi) {
    unsigned long long r;
    asm("mov.b64 %0, {%1,%2};" : "=l"(r) : "f"(lo), "f"(hi));
    return r;
}
__device__ __forceinline__ void upk2(unsigned long long v, float &lo, float &hi) {
    asm("mov.b64 {%0,%1}, %2;" : "=f"(lo), "=f"(hi) : "l"(v));
}
__device__ __forceinline__ void ffma2(unsigned long long &d, unsigned long long a,
                                      unsigned long long b) {
    asm("fma.rn.f32x2 %0, %1, %2, %0;" : "+l"(d) : "l"(a), "l"(b));
}

// =================================================================================
// Kernel A: fused LayerNorm(inputs) + K/V projection.
// grid = 2048 blocks x2 launches (64 rows each), 128 threads.
// (split into two launches so ncu's fixed -s 5 capture window lands on attn)
// =================================================================================
__global__ void __launch_bounds__(128) proj_kv(
    const float* __restrict__ x, const float* __restrict__ Wk, const float* __restrict__ bk,
    const float* __restrict__ Wv, const float* __restrict__ bv,
    const float* __restrict__ g, const float* __restrict__ be, int blockoff)
{
    extern __shared__ float sm[];
    float* xs  = sm;               // 64*68
    float* ws  = xs + 64 * 68;     // 128*68 (Wk rows 0..63, Wv rows 64..127)
    float* rm  = ws + 128 * 68;    // 64
    float* ri  = rm + 64;          // 64
    float* gs  = ri + 64;          // 64
    float* bes = gs + 64;          // 64
    float* bkv = bes + 64;         // 128

    const int tid = threadIdx.x;
    const int rowbase = (blockIdx.x + blockoff) * 64;

    // vectorized loads: weights (2048 float4) and x tile (1024 float4)
    {
        const float4* wk4 = (const float4*)Wk;
        const float4* wv4 = (const float4*)Wv;
        #pragma unroll
        for (int q = 0; q < 16; q++) {
            int i = tid + 128 * q;            // float4 index, 0..2047
            int r = i >> 4, d = (i & 15) * 4;
            float4 v = (i < 1024) ? wk4[i] : wv4[i - 1024];
            *(float4*)&ws[r * 68 + d] = v;
        }
        const float4* xg = (const float4*)(x + rowbase * 64);
        #pragma unroll
        for (int q = 0; q < 8; q++) {
            int i = tid + 128 * q;            // 0..1023
            int r = i >> 4, d = (i & 15) * 4;
            *(float4*)&xs[r * 68 + d] = xg[i];
        }
    }
    if (tid < 64) {
        gs[tid] = g[tid]; bes[tid] = be[tid];
        bkv[tid] = bk[tid]; bkv[64 + tid] = bv[tid];
    }
    __syncthreads();

    {   // row stats: 2 threads per row
        int r = tid >> 1, h = tid & 1;
        float s = 0.f, sq = 0.f;
        const float* row = &xs[r * 68 + h * 32];
        #pragma unroll
        for (int d = 0; d < 32; d++) { float v = row[d]; s += v; sq += v * v; }
        s  += __shfl_xor_sync(0xffffffffu, s, 1);
        sq += __shfl_xor_sync(0xffffffffu, sq, 1);
        if (h == 0) {
            float m = s * (1.f / 64.f);
            float var = sq * (1.f / 64.f) - m * m;
            rm[r] = m; ri[r] = rsqrtf(var + LN_EPS);
        }
    }
    __syncthreads();
    for (int i = tid; i < 4096; i += 128) {
        int r = i >> 6, d = i & 63;
        xs[r * 68 + d] = (xs[r * 68 + d] - rm[r]) * ri[r] * gs[d] + bes[d];
    }
    __syncthreads();

    const int tx = tid & 15, ty = tid >> 4;
    unsigned long long acc[4][8];   // [row-pair][j] : {row ty+16kp, row ty+16kp+8}
    #pragma unroll
    for (int kp = 0; kp < 4; kp++)
        #pragma unroll
        for (int j = 0; j < 8; j++) acc[kp][j] = 0ull;

    #pragma unroll 2
    for (int d = 0; d < 64; d += 4) {
        unsigned long long aa[4][4];   // [kp][e]
        #pragma unroll
        for (int kp = 0; kp < 4; kp++) {
            float4 a0 = *(const float4*)&xs[(ty + 16 * kp) * 68 + d];
            float4 a1 = *(const float4*)&xs[(ty + 16 * kp + 8) * 68 + d];
            aa[kp][0] = pk2(a0.x, a1.x);
            aa[kp][1] = pk2(a0.y, a1.y);
            aa[kp][2] = pk2(a0.z, a1.z);
            aa[kp][3] = pk2(a0.w, a1.w);
        }
        #pragma unroll
        for (int j = 0; j < 8; j++) {
            float4 b4 = *(const float4*)&ws[(tx + 16 * j) * 68 + d];
            unsigned long long bb;
            bb = pk2(b4.x, b4.x);
            #pragma unroll
            for (int kp = 0; kp < 4; kp++) ffma2(acc[kp][j], aa[kp][0], bb);
            bb = pk2(b4.y, b4.y);
            #pragma unroll
            for (int kp = 0; kp < 4; kp++) ffma2(acc[kp][j], aa[kp][1], bb);
            bb = pk2(b4.z, b4.z);
            #pragma unroll
            for (int kp = 0; kp < 4; kp++) ffma2(acc[kp][j], aa[kp][2], bb);
            bb = pk2(b4.w, b4.w);
            #pragma unroll
            for (int kp = 0; kp < 4; kp++) ffma2(acc[kp][j], aa[kp][3], bb);
        }
    }

    #pragma unroll
    for (int kp = 0; kp < 4; kp++) {
        #pragma unroll
        for (int j = 0; j < 8; j++) {
            float lo, hi; upk2(acc[kp][j], lo, hi);
            int c = tx + 16 * j;
            int r0 = rowbase + ty + 16 * kp;
            int r1 = r0 + 8;
            float bias = bkv[c];
            float v0 = lo + bias, v1 = hi + bias;
            if (c < 64) {
                g_K[r0 * 64 + c] = v0;
                g_K[r1 * 64 + c] = v1;
            } else {
                g_V[r0 * 64 + (c - 64)] = v0;
                g_V[r1 * 64 + (c - 64)] = v1;
            }
        }
    }
}

// =================================================================================
// Kernel B: slots init + LN + first q projection. 448 blocks (one per slot-row),
// 64 threads. Weights straight from gmem (L2-resident across blocks).
// =================================================================================
__global__ void __launch_bounds__(64) init_kernel(
    const float* __restrict__ noise, const float* __restrict__ mu,
    const float* __restrict__ sigma, const float* __restrict__ Wq,
    const float* __restrict__ bq, const float* __restrict__ g_sl,
    const float* __restrict__ be_sl)
{
    __shared__ float ss[64];
    __shared__ float sl[64];
    const int tid = threadIdx.x;
    const int row = blockIdx.x;

    float v = mu[tid] + sigma[tid] * noise[row * 64 + tid];
    sl[tid] = v;
    g_slots[row * 64 + tid] = v;
    __syncthreads();

    if (tid < 32) {   // warp 0: LN over the 64-dim row
        float x0 = sl[tid], x1 = sl[tid + 32];
        float s = x0 + x1, sq = x0 * x0 + x1 * x1;
        #pragma unroll
        for (int o = 16; o > 0; o >>= 1) {
            s  += __shfl_xor_sync(0xffffffffu, s, o);
            sq += __shfl_xor_sync(0xffffffffu, sq, o);
        }
        float m = s * (1.f / 64.f);
        float var = sq * (1.f / 64.f) - m * m;
        float rin = rsqrtf(var + LN_EPS);
        ss[tid]      = (x0 - m) * rin * g_sl[tid]      + be_sl[tid];
        ss[tid + 32] = (x1 - m) * rin * g_sl[tid + 32] + be_sl[tid + 32];
    }
    __syncthreads();

    {   // q = LN(slots) @ Wq^T + bq ; thread tid -> output channel tid
        float acc = bq[tid];
        const float* w = Wq + tid * 64;
        #pragma unroll 16
        for (int d = 0; d < 64; d++) acc += ss[d] * w[d];
        g_Q[row * 64 + tid] = acc;
    }
}

// =================================================================================
// Kernel C: streaming attention with register double-buffer prefetch.
// grid = (CH, B), 256 threads. Warp i (<7) owns slot i; lane c owns channels
// c and c+32. Softmax over slots is local per position; renorm deferred via S.
// =================================================================================
__global__ void __launch_bounds__(256) attn_kernel()
{
    __shared__ float qs[7 * 64];
    __shared__ float ks[64 * 65];
    __shared__ float vs[64 * 65];
    __shared__ float at[7 * 64];

    const int tid = threadIdx.x;
    const int b = blockIdx.y, ch = blockIdx.x;
    const int wi = tid >> 5, c = tid & 31;

    for (int i = tid; i < 448; i += 256) qs[i] = g_Q[b * 448 + i];

    float U0 = 0.f, U1 = 0.f, Sa = 0.f;
    const int base = (b * 4096 + ch * 256) * 64;
    const float4* Kg = (const float4*)(g_K + base);
    const float4* Vg = (const float4*)(g_V + base);

    // prefetch tile 0 into registers (4 float4 per array per thread)
    float4 rk[4], rv[4];
    #pragma unroll
    for (int q = 0; q < 4; q++) {
        rk[q] = Kg[tid + 256 * q];
        rv[q] = Vg[tid + 256 * q];
    }

    for (int t = 0; t < 4; t++) {
        __syncthreads();   // previous tile's consumers done with ks/vs/at
        #pragma unroll
        for (int q = 0; q < 4; q++) {      // publish registers -> smem (stride 65)
            int idx = tid + 256 * q;
            int r = idx >> 4, d = (idx & 15) * 4;
            float* pk = &ks[r * 65 + d];
            pk[0] = rk[q].x; pk[1] = rk[q].y; pk[2] = rk[q].z; pk[3] = rk[q].w;
            float* pv = &vs[r * 65 + d];
            pv[0] = rv[q].x; pv[1] = rv[q].y; pv[2] = rv[q].z; pv[3] = rv[q].w;
        }
        __syncthreads();

        if (t < 3) {   // prefetch next tile; LDG latency hides under compute below
            #pragma unroll
            for (int q = 0; q < 4; q++) {
                rk[q] = Kg[1024 * (t + 1) + tid + 256 * q];
                rv[q] = Vg[1024 * (t + 1) + tid + 256 * q];
            }
        }

        if (wi < 7) {   // dots for positions j=c and j=c+32
            float d0 = 0.f, d1 = 0.f;
            const float* qrow = &qs[wi * 64];
            const float* k0 = &ks[c * 65];
            const float* k1 = &ks[(c + 32) * 65];
            #pragma unroll 16
            for (int d = 0; d < 64; d++) {
                float q = qrow[d];
                d0 += q * k0[d];
                d1 += q * k1[d];
            }
            at[wi * 64 + c]      = d0 * 0.125f;
            at[wi * 64 + c + 32] = d1 * 0.125f;
        }
        __syncthreads();

        if (tid < 64) {   // softmax over the 7 slots for position j=tid
            float v[7];
            #pragma unroll
            for (int i = 0; i < 7; i++) v[i] = at[i * 64 + tid];
            float m = v[0];
            #pragma unroll
            for (int i = 1; i < 7; i++) m = fmaxf(m, v[i]);
            float s = 0.f;
            #pragma unroll
            for (int i = 0; i < 7; i++) { v[i] = __expf(v[i] - m); s += v[i]; }
            float inv = 1.f / s;
            #pragma unroll
            for (int i = 0; i < 7; i++) at[i * 64 + tid] = v[i] * inv + ATT_EPS;
        }
        __syncthreads();

        if (wi < 7) {   // accumulate partial updates
            const float* arow = &at[wi * 64];
            #pragma unroll 8
            for (int j = 0; j < 64; j++) {
                float a = arow[j];
                Sa += a;
                U0 += a * vs[j * 65 + c];
                U1 += a * vs[j * 65 + c + 32];
            }
        }
    }

    if (wi < 7) {
        int o = ((b * CH + ch) * 7 + wi) * 64;
        g_Up[o + c]      = U0;
        g_Up[o + c + 32] = U1;
        if (c == 0) g_Sp[(b * CH + ch) * 7 + wi] = Sa;
    }
}

// =================================================================================
// Kernel D: reduce partials + GRU + LN + MLP residual + (next-iter LN + q proj).
// grid 448 (one block per slot-row), 192 threads, no smem weight staging
// (weights served from L2, ~160 KB/block, shared across all 448 blocks).
// =================================================================================
__global__ void __launch_bounds__(192) update_kernel(
    const float* __restrict__ W_ih, const float* __restrict__ W_hh,
    const float* __restrict__ b_ih, const float* __restrict__ b_hh,
    const float* __restrict__ W1, const float* __restrict__ b1,
    const float* __restrict__ W2, const float* __restrict__ b2,
    const float* __restrict__ Wq, const float* __restrict__ bq,
    const float* __restrict__ g_sl, const float* __restrict__ be_sl,
    const float* __restrict__ g_ff, const float* __restrict__ be_ff,
    int last, float* __restrict__ out)
{
    __shared__ float upd[64];     // raw partial-sum (unscaled); invS folded into gi
    __shared__ float slp[64];
    __shared__ float gi[192];
    __shared__ float gh[192];
    __shared__ float sln[64];
    __shared__ float ff[64];
    __shared__ float h1[128];
    __shared__ float invS;

    const int tid = threadIdx.x;
    const int row = blockIdx.x;            // b*7 + i
    const int b = row / 7, i = row % 7;

    // Phase 1: reduce attention partials (fixed chunk order) + slots load + 1/S
    if (tid < 64) {
        float u = 0.f;
        #pragma unroll
        for (int chn = 0; chn < CH; chn++)
            u += g_Up[((b * CH + chn) * 7 + i) * 64 + tid];
        upd[tid] = u;
        slp[tid] = g_slots[row * 64 + tid];
    } else if (tid < 96) {                 // warp 2 (fully convergent branch)
        int lane = tid - 64;
        float sp = (lane < CH) ? g_Sp[(b * CH + lane) * 7 + i] : 0.f;
        #pragma unroll
        for (int o = 8; o > 0; o >>= 1) sp += __shfl_xor_sync(0xffffffffu, sp, o);
        if (lane == 0) invS = 1.f / sp;
    }
    __syncthreads();

    // Phase 2: GRU gate pre-activations; thread o in [0,192)
    {
        float du = 0.f, ah = b_hh[tid];
        const float* wa = W_ih + tid * 64;
        const float* wb = W_hh + tid * 64;
        #pragma unroll 16
        for (int d = 0; d < 64; d++) {
            du += upd[d] * wa[d];          // dot with raw sum; scale after (linear)
            ah += slp[d] * wb[d];
        }
        gi[tid] = b_ih[tid] + invS * du;
        gh[tid] = ah;
    }
    __syncthreads();

    // Phase 3: GRU combine (tid<64)
    if (tid < 64) {
        float xr = gi[tid] + gh[tid];
        float xz = gi[64 + tid] + gh[64 + tid];
        float r = 1.f / (1.f + __expf(-xr));
        float z = 1.f / (1.f + __expf(-xz));
        float n = tanhf(gi[128 + tid] + r * gh[128 + tid]);
        sln[tid] = (1.f - z) * n + z * slp[tid];
    }
    __syncthreads();

    // Phase 4: LN(slots_new) with g_ff/be_ff -> ff   (warp 0)
    if (tid < 32) {
        float x0 = sln[tid], x1 = sln[tid + 32];
        float s = x0 + x1, sq = x0 * x0 + x1 * x1;
        #pragma unroll
        for (int o = 16; o > 0; o >>= 1) {
            s  += __shfl_xor_sync(0xffffffffu, s, o);
            sq += __shfl_xor_sync(0xffffffffu, sq, o);
        }
        float m = s * (1.f / 64.f);
        float var = sq * (1.f / 64.f) - m * m;
        float rin = rsqrtf(var + LN_EPS);
        ff[tid]      = (x0 - m) * rin * g_ff[tid]      + be_ff[tid];
        ff[tid + 32] = (x1 - m) * rin * g_ff[tid + 32] + be_ff[tid + 32];
    }
    __syncthreads();

    // Phase 5: h1 = relu(ff @ W1^T + b1)   (tid<128)
    if (tid < 128) {
        float acc = b1[tid];
        const float* w = W1 + tid * 64;
        #pragma unroll 16
        for (int d = 0; d < 64; d++) acc += ff[d] * w[d];
        h1[tid] = fmaxf(acc, 0.f);
    }
    __syncthreads();

    // Phase 6: out proj + residual   (tid<64)
    if (tid < 64) {
        float acc = b2[tid];
        const float* w = W2 + tid * 128;
        #pragma unroll 16
        for (int h = 0; h < 128; h++) acc += h1[h] * w[h];
        float v = sln[tid] + acc;
        g_slots[row * 64 + tid] = v;
        upd[tid] = v;                       // reuse as slot_final
        if (last) out[row * 64 + tid] = v;
    }
    __syncthreads();

    if (!last) {
        // Phase 7a: LN(slot_final) with g_sl/be_sl -> ff   (warp 0)
        if (tid < 32) {
            float x0 = upd[tid], x1 = upd[tid + 32];
            float s = x0 + x1, sq = x0 * x0 + x1 * x1;
            #pragma unroll
            for (int o = 16; o > 0; o >>= 1) {
                s  += __shfl_xor_sync(0xffffffffu, s, o);
                sq += __shfl_xor_sync(0xffffffffu, sq, o);
            }
            float m = s * (1.f / 64.f);
            float var = sq * (1.f / 64.f) - m * m;
            float rin = rsqrtf(var + LN_EPS);
            ff[tid]      = (x0 - m) * rin * g_sl[tid]      + be_sl[tid];
            ff[tid + 32] = (x1 - m) * rin * g_sl[tid + 32] + be_sl[tid + 32];
        }
        __syncthreads();
        // Phase 7b: q = ff @ Wq^T + bq   (tid<64)
        if (tid < 64) {
            float acc = bq[tid];
            const float* w = Wq + tid * 64;
            #pragma unroll 16
            for (int d = 0; d < 64; d++) acc += ff[d] * w[d];
            g_Q[row * 64 + tid] = acc;
        }
    }
}

// =================================================================================
extern "C" void kernel_launch(void* const* d_in, const int* in_sizes, int n_in,
                              void* d_out, int out_size)
{
    const float* inputs = (const float*)d_in[0];
    // d_in[1] = positional_embeddings (unused by reference)
    const float* noise  = (const float*)d_in[2];
    const float* mu     = (const float*)d_in[3];
    const float* sigma  = (const float*)d_in[4];
    const float* Wq     = (const float*)d_in[5];
    const float* bq     = (const float*)d_in[6];
    const float* Wk     = (const float*)d_in[7];
    const float* bk     = (const float*)d_in[8];
    const float* Wv     = (const float*)d_in[9];
    const float* bv     = (const float*)d_in[10];
    const float* W_ih   = (const float*)d_in[11];
    const float* W_hh   = (const float*)d_in[12];
    const float* b_ih   = (const float*)d_in[13];
    const float* b_hh   = (const float*)d_in[14];
    const float* W1     = (const float*)d_in[15];
    const float* b1     = (const float*)d_in[16];
    const float* W2     = (const float*)d_in[17];
    const float* b2     = (const float*)d_in[18];
    const float* g_in   = (const float*)d_in[19];
    const float* be_in  = (const float*)d_in[20];
    const float* g_sl   = (const float*)d_in[21];
    const float* be_sl  = (const float*)d_in[22];
    const float* g_ff   = (const float*)d_in[23];
    const float* be_ff  = (const float*)d_in[24];
    float* out = (float*)d_out;

    const int SMEM_A = 13440 * 4;    // proj_kv
    cudaFuncSetAttribute(proj_kv, cudaFuncAttributeMaxDynamicSharedMemorySize, SMEM_A);

    // proj split into two launches: shifts the fixed ncu -s 5 -c 1 capture
    // window onto attn_kernel (launch #5 = attn#2) for next round's profile.
    proj_kv<<<2048, 128, SMEM_A>>>(inputs, Wk, bk, Wv, bv, g_in, be_in, 0);
    proj_kv<<<2048, 128, SMEM_A>>>(inputs, Wk, bk, Wv, bv, g_in, be_in, 2048);
    init_kernel<<<BSZ * NSL, 64>>>(noise, mu, sigma, Wq, bq, g_sl, be_sl);
    for (int it = 0; it < 3; it++) {
        attn_kernel<<<dim3(CH, BSZ), 256>>>();
        update_kernel<<<BSZ * NSL, 192>>>(W_ih, W_hh, b_ih, b_hh, W1, b1, W2, b2,
                                          Wq, bq, g_sl, be_sl, g_ff, be_ff,
                                          (it == 2) ? 1 : 0, out);
    }
}

// round 9
// speedup vs baseline: 1.2939x; 1.2939x over previous
#include <cuda_runtime.h>

#define BSZ 64
#define NSEQ 4096
#define DM 64
#define NSL 7
#define HH 128
#define CH 16          // chunks of N per batch for attention
#define LN_EPS 1e-5f
#define ATT_EPS 1e-8f

// ---------------- scratch ----------------
__device__ float g_K[BSZ * NSEQ * DM];            // 67 MB
__device__ float g_V[BSZ * NSEQ * DM];            // 67 MB
__device__ float g_Q[BSZ * NSL * DM];
__device__ float g_slots[BSZ * NSL * DM];
__device__ float g_Up[BSZ * CH * NSL * DM];
__device__ float g_Sp[BSZ * CH * NSL];

// ---------------- packed f32x2 helpers (sm_103a FFMA2 path) ---------------------
__device__ __forceinline__ unsigned long long pk2(float lo, float hi) {
    unsigned long long r;
    asm("mov.b64 %0, {%1,%2};" : "=l"(r) : "f"(lo), "f"(hi));
    return r;
}
__device__ __forceinline__ void upk2(unsigned long long v, float &lo, float &hi) {
    asm("mov.b64 {%0,%1}, %2;" : "=f"(lo), "=f"(hi) : "l"(v));
}
__device__ __forceinline__ void ffma2(unsigned long long &d, unsigned long long a,
                                      unsigned long long b) {
    asm("fma.rn.f32x2 %0, %1, %2, %0;" : "+l"(d) : "l"(a), "l"(b));
}

// ---------------- warp-cooperative dot helpers (coalesced gmem weight rows) -----
__device__ __forceinline__ float warp_dot64(const float* __restrict__ w,
                                            const float* __restrict__ xs, int lane) {
    float p = fmaf(w[lane], xs[lane], w[lane + 32] * xs[lane + 32]);
    #pragma unroll
    for (int o = 16; o > 0; o >>= 1) p += __shfl_xor_sync(0xffffffffu, p, o);
    return p;
}
__device__ __forceinline__ float warp_dot128(const float* __restrict__ w,
                                             const float* __restrict__ xs, int lane) {
    float p = fmaf(w[lane], xs[lane], w[lane + 32] * xs[lane + 32]);
    p = fmaf(w[lane + 64], xs[lane + 64], p);
    p = fmaf(w[lane + 96], xs[lane + 96], p);
    #pragma unroll
    for (int o = 16; o > 0; o >>= 1) p += __shfl_xor_sync(0xffffffffu, p, o);
    return p;
}

// =================================================================================
// Kernel A: fused LayerNorm(inputs) + K/V projection. (unchanged this round)
// grid = 2048 blocks x2 launches (64 rows each), 128 threads.
// =================================================================================
__global__ void __launch_bounds__(128) proj_kv(
    const float* __restrict__ x, const float* __restrict__ Wk, const float* __restrict__ bk,
    const float* __restrict__ Wv, const float* __restrict__ bv,
    const float* __restrict__ g, const float* __restrict__ be, int blockoff)
{
    extern __shared__ float sm[];
    float* xs  = sm;               // 64*68
    float* ws  = xs + 64 * 68;     // 128*68
    float* rm  = ws + 128 * 68;
    float* ri  = rm + 64;
    float* gs  = ri + 64;
    float* bes = gs + 64;
    float* bkv = bes + 64;

    const int tid = threadIdx.x;
    const int rowbase = (blockIdx.x + blockoff) * 64;

    {
        const float4* wk4 = (const float4*)Wk;
        const float4* wv4 = (const float4*)Wv;
        #pragma unroll
        for (int q = 0; q < 16; q++) {
            int i = tid + 128 * q;
            int r = i >> 4, d = (i & 15) * 4;
            float4 v = (i < 1024) ? wk4[i] : wv4[i - 1024];
            *(float4*)&ws[r * 68 + d] = v;
        }
        const float4* xg = (const float4*)(x + rowbase * 64);
        #pragma unroll
        for (int q = 0; q < 8; q++) {
            int i = tid + 128 * q;
            int r = i >> 4, d = (i & 15) * 4;
            *(float4*)&xs[r * 68 + d] = xg[i];
        }
    }
    if (tid < 64) {
        gs[tid] = g[tid]; bes[tid] = be[tid];
        bkv[tid] = bk[tid]; bkv[64 + tid] = bv[tid];
    }
    __syncthreads();

    {
        int r = tid >> 1, h = tid & 1;
        float s = 0.f, sq = 0.f;
        const float* row = &xs[r * 68 + h * 32];
        #pragma unroll
        for (int d = 0; d < 32; d++) { float v = row[d]; s += v; sq += v * v; }
        s  += __shfl_xor_sync(0xffffffffu, s, 1);
        sq += __shfl_xor_sync(0xffffffffu, sq, 1);
        if (h == 0) {
            float m = s * (1.f / 64.f);
            float var = sq * (1.f / 64.f) - m * m;
            rm[r] = m; ri[r] = rsqrtf(var + LN_EPS);
        }
    }
    __syncthreads();
    for (int i = tid; i < 4096; i += 128) {
        int r = i >> 6, d = i & 63;
        xs[r * 68 + d] = (xs[r * 68 + d] - rm[r]) * ri[r] * gs[d] + bes[d];
    }
    __syncthreads();

    const int tx = tid & 15, ty = tid >> 4;
    unsigned long long acc[4][8];
    #pragma unroll
    for (int kp = 0; kp < 4; kp++)
        #pragma unroll
        for (int j = 0; j < 8; j++) acc[kp][j] = 0ull;

    #pragma unroll 2
    for (int d = 0; d < 64; d += 4) {
        unsigned long long aa[4][4];
        #pragma unroll
        for (int kp = 0; kp < 4; kp++) {
            float4 a0 = *(const float4*)&xs[(ty + 16 * kp) * 68 + d];
            float4 a1 = *(const float4*)&xs[(ty + 16 * kp + 8) * 68 + d];
            aa[kp][0] = pk2(a0.x, a1.x);
            aa[kp][1] = pk2(a0.y, a1.y);
            aa[kp][2] = pk2(a0.z, a1.z);
            aa[kp][3] = pk2(a0.w, a1.w);
        }
        #pragma unroll
        for (int j = 0; j < 8; j++) {
            float4 b4 = *(const float4*)&ws[(tx + 16 * j) * 68 + d];
            unsigned long long bb;
            bb = pk2(b4.x, b4.x);
            #pragma unroll
            for (int kp = 0; kp < 4; kp++) ffma2(acc[kp][j], aa[kp][0], bb);
            bb = pk2(b4.y, b4.y);
            #pragma unroll
            for (int kp = 0; kp < 4; kp++) ffma2(acc[kp][j], aa[kp][1], bb);
            bb = pk2(b4.z, b4.z);
            #pragma unroll
            for (int kp = 0; kp < 4; kp++) ffma2(acc[kp][j], aa[kp][2], bb);
            bb = pk2(b4.w, b4.w);
            #pragma unroll
            for (int kp = 0; kp < 4; kp++) ffma2(acc[kp][j], aa[kp][3], bb);
        }
    }

    #pragma unroll
    for (int kp = 0; kp < 4; kp++) {
        #pragma unroll
        for (int j = 0; j < 8; j++) {
            float lo, hi; upk2(acc[kp][j], lo, hi);
            int c = tx + 16 * j;
            int r0 = rowbase + ty + 16 * kp;
            int r1 = r0 + 8;
            float bias = bkv[c];
            float v0 = lo + bias, v1 = hi + bias;
            if (c < 64) {
                g_K[r0 * 64 + c] = v0;
                g_K[r1 * 64 + c] = v1;
            } else {
                g_V[r0 * 64 + (c - 64)] = v0;
                g_V[r1 * 64 + (c - 64)] = v1;
            }
        }
    }
}

// =================================================================================
// Kernel B: slots init + LN + first q projection. 448 blocks, 256 threads.
// Warp-cooperative q-proj: coalesced Wq row reads.
// =================================================================================
__global__ void __launch_bounds__(256) init_kernel(
    const float* __restrict__ noise, const float* __restrict__ mu,
    const float* __restrict__ sigma, const float* __restrict__ Wq,
    const float* __restrict__ bq, const float* __restrict__ g_sl,
    const float* __restrict__ be_sl)
{
    __shared__ float sl[64];
    __shared__ float ss[64];
    const int tid = threadIdx.x, wid = tid >> 5, lane = tid & 31;
    const int row = blockIdx.x;

    if (tid < 64) {
        float v = mu[tid] + sigma[tid] * noise[row * 64 + tid];
        sl[tid] = v;
        g_slots[row * 64 + tid] = v;
    }
    __syncthreads();

    if (tid < 32) {
        float x0 = sl[tid], x1 = sl[tid + 32];
        float s = x0 + x1, sq = x0 * x0 + x1 * x1;
        #pragma unroll
        for (int o = 16; o > 0; o >>= 1) {
            s  += __shfl_xor_sync(0xffffffffu, s, o);
            sq += __shfl_xor_sync(0xffffffffu, sq, o);
        }
        float m = s * (1.f / 64.f);
        float var = sq * (1.f / 64.f) - m * m;
        float rin = rsqrtf(var + LN_EPS);
        ss[tid]      = (x0 - m) * rin * g_sl[tid]      + be_sl[tid];
        ss[tid + 32] = (x1 - m) * rin * g_sl[tid + 32] + be_sl[tid + 32];
    }
    __syncthreads();

    #pragma unroll 2
    for (int k = 0; k < 8; k++) {
        int o = wid * 8 + k;
        float q = warp_dot64(Wq + o * 64, ss, lane);
        if (lane == 0) g_Q[row * 64 + o] = q + bq[o];
    }
}

// =================================================================================
// Kernel C: "regflow" streaming attention. grid = (CH, B), 256 threads.
// Group of 16 lanes owns one position per q-step; K/V stay in load registers
// (never touch smem); dots via shfl butterfly; softmax local in registers.
// ZERO barriers in the hot loop; one block reduction at the end.
// =================================================================================
__global__ void __launch_bounds__(256) attn_kernel()
{
    __shared__ float qsm[448];
    __shared__ float red[16][464];     // per-group U partials (stride 464: STS.128 ok)
    __shared__ float sred[16][8];      // per-group S partials

    const int tid = threadIdx.x;
    const int b = blockIdx.y, ch = blockIdx.x;
    const int g = tid >> 4;            // group 0..15 (one position per q-step)
    const int s = tid & 15;            // d-block index (4 floats)

    for (int i = tid; i < 448; i += 256) qsm[i] = g_Q[b * 448 + i];
    __syncthreads();

    float4 q4[7];
    #pragma unroll
    for (int i = 0; i < 7; i++) q4[i] = *(const float4*)&qsm[i * 64 + 4 * s];

    float4 U[7];
    float Ss[7];
    #pragma unroll
    for (int i = 0; i < 7; i++) {
        U[i] = make_float4(0.f, 0.f, 0.f, 0.f);
        Ss[i] = 0.f;
    }

    const int pbase = b * 4096 + ch * 256;
    const float4* Kg = (const float4*)g_K + pbase * 16;
    const float4* Vg = (const float4*)g_V + pbase * 16;
    const int off0 = g * 16 + s;       // warp-contiguous: float4 idx = 32w + lane

    float4 k4 = Kg[off0];
    float4 v4 = Vg[off0];

    #pragma unroll 2
    for (int q = 0; q < 16; q++) {
        float4 k4n = k4, v4n = v4;
        if (q < 15) {                   // prefetch next position's K/V row slice
            k4n = Kg[off0 + 256 * (q + 1)];
            v4n = Vg[off0 + 256 * (q + 1)];
        }

        float a[7];
        #pragma unroll
        for (int i = 0; i < 7; i++) {   // dot over d: 4 local + 4-level butterfly
            float t = fmaf(q4[i].x, k4.x, fmaf(q4[i].y, k4.y,
                      fmaf(q4[i].z, k4.z, q4[i].w * k4.w)));
            t += __shfl_xor_sync(0xffffffffu, t, 1);
            t += __shfl_xor_sync(0xffffffffu, t, 2);
            t += __shfl_xor_sync(0xffffffffu, t, 4);
            t += __shfl_xor_sync(0xffffffffu, t, 8);
            a[i] = t * 0.125f;
        }

        // softmax over the 7 slots — fully local (identical on all 16 lanes)
        float mx = a[0];
        #pragma unroll
        for (int i = 1; i < 7; i++) mx = fmaxf(mx, a[i]);
        float ssum = 0.f;
        #pragma unroll
        for (int i = 0; i < 7; i++) { a[i] = __expf(a[i] - mx); ssum += a[i]; }
        float inv = 1.f / ssum;

        #pragma unroll
        for (int i = 0; i < 7; i++) {
            float ai = a[i] * inv + ATT_EPS;
            Ss[i] += ai;
            U[i].x = fmaf(ai, v4.x, U[i].x);
            U[i].y = fmaf(ai, v4.y, U[i].y);
            U[i].z = fmaf(ai, v4.z, U[i].z);
            U[i].w = fmaf(ai, v4.w, U[i].w);
        }
        k4 = k4n; v4 = v4n;
    }

    // block reduction over the 16 groups
    #pragma unroll
    for (int i = 0; i < 7; i++)
        *(float4*)&red[g][i * 64 + 4 * s] = U[i];
    if (s == 0) {
        #pragma unroll
        for (int i = 0; i < 7; i++) sred[g][i] = Ss[i];
    }
    __syncthreads();

    for (int idx = tid; idx < 448; idx += 256) {
        int i = idx >> 6, d = idx & 63;
        float u = 0.f;
        #pragma unroll
        for (int gg = 0; gg < 16; gg++) u += red[gg][i * 64 + d];
        g_Up[((b * CH + ch) * 7 + i) * 64 + d] = u;
    }
    if (tid < 7) {
        float sv = 0.f;
        #pragma unroll
        for (int gg = 0; gg < 16; gg++) sv += sred[gg][tid];
        g_Sp[(b * CH + ch) * 7 + tid] = sv;
    }
}

// =================================================================================
// Kernel D: reduce partials + GRU + LN + MLP residual + (next-iter LN + q proj).
// 448 blocks, 256 threads (8 warps). ALL weight dots warp-cooperative:
// coalesced 128B row reads (fixes R8's stride-256B gather, nL 32 -> 1).
// =================================================================================
__global__ void __launch_bounds__(256) update_kernel(
    const float* __restrict__ W_ih, const float* __restrict__ W_hh,
    const float* __restrict__ b_ih, const float* __restrict__ b_hh,
    const float* __restrict__ W1, const float* __restrict__ b1,
    const float* __restrict__ W2, const float* __restrict__ b2,
    const float* __restrict__ Wq, const float* __restrict__ bq,
    const float* __restrict__ g_sl, const float* __restrict__ be_sl,
    const float* __restrict__ g_ff, const float* __restrict__ be_ff,
    int last, float* __restrict__ out)
{
    __shared__ float upd[64];     // raw partial-sum; invS folded into gi (linear)
    __shared__ float slp[64];
    __shared__ float gi[192];
    __shared__ float gh[192];
    __shared__ float sln[64];
    __shared__ float ff[64];
    __shared__ float h1[128];
    __shared__ float invS;

    const int tid = threadIdx.x, wid = tid >> 5, lane = tid & 31;
    const int row = blockIdx.x;            // b*7 + i
    const int b = row / 7, i = row % 7;

    // Phase 1: reduce attention partials (coalesced) + slots load + 1/S
    if (tid < 64) {
        float u = 0.f;
        #pragma unroll
        for (int chn = 0; chn < CH; chn++)
            u += g_Up[((b * CH + chn) * 7 + i) * 64 + tid];
        upd[tid] = u;
        slp[tid] = g_slots[row * 64 + tid];
    } else if (tid < 96) {
        int l2 = tid - 64;
        float sp = (l2 < CH) ? g_Sp[(b * CH + l2) * 7 + i] : 0.f;
        #pragma unroll
        for (int o = 8; o > 0; o >>= 1) sp += __shfl_xor_sync(0xffffffffu, sp, o);
        if (l2 == 0) invS = 1.f / sp;
    }
    __syncthreads();

    // Phase 2: GRU gate pre-activations; 8 warps x 24 outputs, warp-coop dots
    {
        float vS = invS;
        #pragma unroll 2
        for (int k = 0; k < 24; k++) {
            int o = wid * 24 + k;
            float du = warp_dot64(W_ih + o * 64, upd, lane);
            float ah = warp_dot64(W_hh + o * 64, slp, lane);
            if (lane == 0) { gi[o] = b_ih[o] + vS * du; gh[o] = b_hh[o] + ah; }
        }
    }
    __syncthreads();

    // Phase 3: GRU combine (tid<64)
    if (tid < 64) {
        float xr = gi[tid] + gh[tid];
        float xz = gi[64 + tid] + gh[64 + tid];
        float r = 1.f / (1.f + __expf(-xr));
        float z = 1.f / (1.f + __expf(-xz));
        float n = tanhf(gi[128 + tid] + r * gh[128 + tid]);
        sln[tid] = (1.f - z) * n + z * slp[tid];
    }
    __syncthreads();

    // Phase 4: LN(slots_new) with g_ff/be_ff -> ff (warp 0)
    if (tid < 32) {
        float x0 = sln[tid], x1 = sln[tid + 32];
        float s = x0 + x1, sq = x0 * x0 + x1 * x1;
        #pragma unroll
        for (int o = 16; o > 0; o >>= 1) {
            s  += __shfl_xor_sync(0xffffffffu, s, o);
            sq += __shfl_xor_sync(0xffffffffu, sq, o);
        }
        float m = s * (1.f / 64.f);
        float var = sq * (1.f / 64.f) - m * m;
        float rin = rsqrtf(var + LN_EPS);
        ff[tid]      = (x0 - m) * rin * g_ff[tid]      + be_ff[tid];
        ff[tid + 32] = (x1 - m) * rin * g_ff[tid + 32] + be_ff[tid + 32];
    }
    __syncthreads();

    // Phase 5: h1 = relu(ff @ W1^T + b1); 8 warps x 16 outputs
    #pragma unroll 2
    for (int k = 0; k < 16; k++) {
        int o = wid * 16 + k;
        float acc = warp_dot64(W1 + o * 64, ff, lane);
        if (lane == 0) h1[o] = fmaxf(acc + b1[o], 0.f);
    }
    __syncthreads();

    // Phase 6: out proj + residual; 8 warps x 8 outputs (dot over 128)
    #pragma unroll 2
    for (int k = 0; k < 8; k++) {
        int o = wid * 8 + k;
        float acc = warp_dot128(W2 + o * 128, h1, lane);
        if (lane == 0) {
            float v = sln[o] + acc + b2[o];
            g_slots[row * 64 + o] = v;
            upd[o] = v;                 // reuse as slot_final
            if (last) out[row * 64 + o] = v;
        }
    }
    __syncthreads();

    if (!last) {
        // Phase 7a: LN(slot_final) with g_sl/be_sl -> ff (warp 0)
        if (tid < 32) {
            float x0 = upd[tid], x1 = upd[tid + 32];
            float s = x0 + x1, sq = x0 * x0 + x1 * x1;
            #pragma unroll
            for (int o = 16; o > 0; o >>= 1) {
                s  += __shfl_xor_sync(0xffffffffu, s, o);
                sq += __shfl_xor_sync(0xffffffffu, sq, o);
            }
            float m = s * (1.f / 64.f);
            float var = sq * (1.f / 64.f) - m * m;
            float rin = rsqrtf(var + LN_EPS);
            ff[tid]      = (x0 - m) * rin * g_sl[tid]      + be_sl[tid];
            ff[tid + 32] = (x1 - m) * rin * g_sl[tid + 32] + be_sl[tid + 32];
        }
        __syncthreads();
        // Phase 7b: q = ff @ Wq^T + bq; 8 warps x 8 outputs
        #pragma unroll 2
        for (int k = 0; k < 8; k++) {
            int o = wid * 8 + k;
            float acc = warp_dot64(Wq + o * 64, ff, lane);
            if (lane == 0) g_Q[row * 64 + o] = acc + bq[o];
        }
    }
}

// =================================================================================
extern "C" void kernel_launch(void* const* d_in, const int* in_sizes, int n_in,
                              void* d_out, int out_size)
{
    const float* inputs = (const float*)d_in[0];
    // d_in[1] = positional_embeddings (unused by reference)
    const float* noise  = (const float*)d_in[2];
    const float* mu     = (const float*)d_in[3];
    const float* sigma  = (const float*)d_in[4];
    const float* Wq     = (const float*)d_in[5];
    const float* bq     = (const float*)d_in[6];
    const float* Wk     = (const float*)d_in[7];
    const float* bk     = (const float*)d_in[8];
    const float* Wv     = (const float*)d_in[9];
    const float* bv     = (const float*)d_in[10];
    const float* W_ih   = (const float*)d_in[11];
    const float* W_hh   = (const float*)d_in[12];
    const float* b_ih   = (const float*)d_in[13];
    const float* b_hh   = (const float*)d_in[14];
    const float* W1     = (const float*)d_in[15];
    const float* b1     = (const float*)d_in[16];
    const float* W2     = (const float*)d_in[17];
    const float* b2     = (const float*)d_in[18];
    const float* g_in   = (const float*)d_in[19];
    const float* be_in  = (const float*)d_in[20];
    const float* g_sl   = (const float*)d_in[21];
    const float* be_sl  = (const float*)d_in[22];
    const float* g_ff   = (const float*)d_in[23];
    const float* be_ff  = (const float*)d_in[24];
    float* out = (float*)d_out;

    const int SMEM_A = 13440 * 4;    // proj_kv
    cudaFuncSetAttribute(proj_kv, cudaFuncAttributeMaxDynamicSharedMemorySize, SMEM_A);

    // proj split kept: ncu's fixed -s 5 -c 1 window lands on attn#2 (launch idx 5)
    proj_kv<<<2048, 128, SMEM_A>>>(inputs, Wk, bk, Wv, bv, g_in, be_in, 0);
    proj_kv<<<2048, 128, SMEM_A>>>(inputs, Wk, bk, Wv, bv, g_in, be_in, 2048);
    init_kernel<<<BSZ * NSL, 256>>>(noise, mu, sigma, Wq, bq, g_sl, be_sl);
    for (int it = 0; it < 3; it++) {
        attn_kernel<<<dim3(CH, BSZ), 256>>>();
        update_kernel<<<BSZ * NSL, 256>>>(W_ih, W_hh, b_ih, b_hh, W1, b1, W2, b2,
                                          Wq, bq, g_sl, be_sl, g_ff, be_ff,
                                          (it == 2) ? 1 : 0, out);
    }
}

// round 11
// speedup vs baseline: 1.3352x; 1.0320x over previous
#include <cuda_runtime.h>

#define BSZ 64
#define NSEQ 4096
#define DM 64
#define NSL 7
#define HH 128
#define CHK 32         // chunks of N per batch for attention (128 positions each)
#define LN_EPS 1e-5f
#define ATT_EPS 1e-8f

// ---------------- scratch ----------------
__device__ float g_K[BSZ * NSEQ * DM];            // 67 MB
__device__ float g_V[BSZ * NSEQ * DM];            // 67 MB
__device__ float g_Q[BSZ * NSL * DM];
__device__ float g_slots[BSZ * NSL * DM];
__device__ float g_Up[BSZ * CHK * NSL * DM];      // 3.7 MB
__device__ float g_Sp[BSZ * CHK * NSL];

// ---------------- packed f32x2 helpers (sm_103a FFMA2 path) ---------------------
__device__ __forceinline__ unsigned long long pk2(float lo, float hi) {
    unsigned long long r;
    asm("mov.b64 %0, {%1,%2};" : "=l"(r) : "f"(lo), "f"(hi));
    return r;
}
__device__ __forceinline__ void upk2(unsigned long long v, float &lo, float &hi) {
    asm("mov.b64 {%0,%1}, %2;" : "=f"(lo), "=f"(hi) : "l"(v));
}
__device__ __forceinline__ void ffma2(unsigned long long &d, unsigned long long a,
                                      unsigned long long b) {
    asm("fma.rn.f32x2 %0, %1, %2, %0;" : "+l"(d) : "l"(a), "l"(b));
}

// ---------------- warp-cooperative dot helpers ----------------------------------
__device__ __forceinline__ float warp_dot64(const float* __restrict__ w,
                                            const float* __restrict__ xs, int lane) {
    float p = fmaf(w[lane], xs[lane], w[lane + 32] * xs[lane + 32]);
    #pragma unroll
    for (int o = 16; o > 0; o >>= 1) p += __shfl_xor_sync(0xffffffffu, p, o);
    return p;
}
__device__ __forceinline__ float warp_dot128(const float* __restrict__ w,
                                             const float* __restrict__ xs, int lane) {
    float p = fmaf(w[lane], xs[lane], w[lane + 32] * xs[lane + 32]);
    p = fmaf(w[lane + 64], xs[lane + 64], p);
    p = fmaf(w[lane + 96], xs[lane + 96], p);
    #pragma unroll
    for (int o = 16; o > 0; o >>= 1) p += __shfl_xor_sync(0xffffffffu, p, o);
    return p;
}

// =================================================================================
// Kernel A: fused LayerNorm(inputs) + K/V projection. (code unchanged;
// split into SIX launches so the ncu -s 5 -c 1 window captures proj itself)
// =================================================================================
__global__ void __launch_bounds__(128) proj_kv(
    const float* __restrict__ x, const float* __restrict__ Wk, const float* __restrict__ bk,
    const float* __restrict__ Wv, const float* __restrict__ bv,
    const float* __restrict__ g, const float* __restrict__ be, int blockoff)
{
    extern __shared__ float sm[];
    float* xs  = sm;               // 64*68
    float* ws  = xs + 64 * 68;     // 128*68
    float* rm  = ws + 128 * 68;
    float* ri  = rm + 64;
    float* gs  = ri + 64;
    float* bes = gs + 64;
    float* bkv = bes + 64;

    const int tid = threadIdx.x;
    const int rowbase = (blockIdx.x + blockoff) * 64;

    {
        const float4* wk4 = (const float4*)Wk;
        const float4* wv4 = (const float4*)Wv;
        #pragma unroll
        for (int q = 0; q < 16; q++) {
            int i = tid + 128 * q;
            int r = i >> 4, d = (i & 15) * 4;
            float4 v = (i < 1024) ? wk4[i] : wv4[i - 1024];
            *(float4*)&ws[r * 68 + d] = v;
        }
        const float4* xg = (const float4*)(x + rowbase * 64);
        #pragma unroll
        for (int q = 0; q < 8; q++) {
            int i = tid + 128 * q;
            int r = i >> 4, d = (i & 15) * 4;
            *(float4*)&xs[r * 68 + d] = xg[i];
        }
    }
    if (tid < 64) {
        gs[tid] = g[tid]; bes[tid] = be[tid];
        bkv[tid] = bk[tid]; bkv[64 + tid] = bv[tid];
    }
    __syncthreads();

    {
        int r = tid >> 1, h = tid & 1;
        float s = 0.f, sq = 0.f;
        const float* row = &xs[r * 68 + h * 32];
        #pragma unroll
        for (int d = 0; d < 32; d++) { float v = row[d]; s += v; sq += v * v; }
        s  += __shfl_xor_sync(0xffffffffu, s, 1);
        sq += __shfl_xor_sync(0xffffffffu, sq, 1);
        if (h == 0) {
            float m = s * (1.f / 64.f);
            float var = sq * (1.f / 64.f) - m * m;
            rm[r] = m; ri[r] = rsqrtf(var + LN_EPS);
        }
    }
    __syncthreads();
    for (int i = tid; i < 4096; i += 128) {
        int r = i >> 6, d = i & 63;
        xs[r * 68 + d] = (xs[r * 68 + d] - rm[r]) * ri[r] * gs[d] + bes[d];
    }
    __syncthreads();

    const int tx = tid & 15, ty = tid >> 4;
    unsigned long long acc[4][8];
    #pragma unroll
    for (int kp = 0; kp < 4; kp++)
        #pragma unroll
        for (int j = 0; j < 8; j++) acc[kp][j] = 0ull;

    #pragma unroll 2
    for (int d = 0; d < 64; d += 4) {
        unsigned long long aa[4][4];
        #pragma unroll
        for (int kp = 0; kp < 4; kp++) {
            float4 a0 = *(const float4*)&xs[(ty + 16 * kp) * 68 + d];
            float4 a1 = *(const float4*)&xs[(ty + 16 * kp + 8) * 68 + d];
            aa[kp][0] = pk2(a0.x, a1.x);
            aa[kp][1] = pk2(a0.y, a1.y);
            aa[kp][2] = pk2(a0.z, a1.z);
            aa[kp][3] = pk2(a0.w, a1.w);
        }
        #pragma unroll
        for (int j = 0; j < 8; j++) {
            float4 b4 = *(const float4*)&ws[(tx + 16 * j) * 68 + d];
            unsigned long long bb;
            bb = pk2(b4.x, b4.x);
            #pragma unroll
            for (int kp = 0; kp < 4; kp++) ffma2(acc[kp][j], aa[kp][0], bb);
            bb = pk2(b4.y, b4.y);
            #pragma unroll
            for (int kp = 0; kp < 4; kp++) ffma2(acc[kp][j], aa[kp][1], bb);
            bb = pk2(b4.z, b4.z);
            #pragma unroll
            for (int kp = 0; kp < 4; kp++) ffma2(acc[kp][j], aa[kp][2], bb);
            bb = pk2(b4.w, b4.w);
            #pragma unroll
            for (int kp = 0; kp < 4; kp++) ffma2(acc[kp][j], aa[kp][3], bb);
        }
    }

    #pragma unroll
    for (int kp = 0; kp < 4; kp++) {
        #pragma unroll
        for (int j = 0; j < 8; j++) {
            float lo, hi; upk2(acc[kp][j], lo, hi);
            int c = tx + 16 * j;
            int r0 = rowbase + ty + 16 * kp;
            int r1 = r0 + 8;
            float bias = bkv[c];
            float v0 = lo + bias, v1 = hi + bias;
            if (c < 64) {
                g_K[r0 * 64 + c] = v0;
                g_K[r1 * 64 + c] = v1;
            } else {
                g_V[r0 * 64 + (c - 64)] = v0;
                g_V[r1 * 64 + (c - 64)] = v1;
            }
        }
    }
}

// =================================================================================
// Kernel B: slots init + LN + first q projection. 448 blocks, 256 threads.
// =================================================================================
__global__ void __launch_bounds__(256) init_kernel(
    const float* __restrict__ noise, const float* __restrict__ mu,
    const float* __restrict__ sigma, const float* __restrict__ Wq,
    const float* __restrict__ bq, const float* __restrict__ g_sl,
    const float* __restrict__ be_sl)
{
    __shared__ float sl[64];
    __shared__ float ss[64];
    const int tid = threadIdx.x, wid = tid >> 5, lane = tid & 31;
    const int row = blockIdx.x;

    if (tid < 64) {
        float v = mu[tid] + sigma[tid] * noise[row * 64 + tid];
        sl[tid] = v;
        g_slots[row * 64 + tid] = v;
    }
    __syncthreads();

    if (tid < 32) {
        float x0 = sl[tid], x1 = sl[tid + 32];
        float s = x0 + x1, sq = x0 * x0 + x1 * x1;
        #pragma unroll
        for (int o = 16; o > 0; o >>= 1) {
            s  += __shfl_xor_sync(0xffffffffu, s, o);
            sq += __shfl_xor_sync(0xffffffffu, sq, o);
        }
        float m = s * (1.f / 64.f);
        float var = sq * (1.f / 64.f) - m * m;
        float rin = rsqrtf(var + LN_EPS);
        ss[tid]      = (x0 - m) * rin * g_sl[tid]      + be_sl[tid];
        ss[tid + 32] = (x1 - m) * rin * g_sl[tid + 32] + be_sl[tid + 32];
    }
    __syncthreads();

    #pragma unroll 2
    for (int k = 0; k < 8; k++) {
        int o = wid * 8 + k;
        float q = warp_dot64(Wq + o * 64, ss, lane);
        if (lane == 0) g_Q[row * 64 + o] = q + bq[o];
    }
}

// =================================================================================
// Kernel C v4: two-phase transposed attention. grid (32, 64), 128 threads.
// Phase A: thread owns position j -> 7 dots with K from smem, softmax local,
//          a-matrix to smem. NO shfl, NO redundancy.
// Phase B: thread owns (group, d-quad) -> V read DIRECT from gmem (coalesced),
//          a via broadcast LDS. Reduction buffer aliases the dead K tile.
// =================================================================================
__global__ void __launch_bounds__(128) attn_kernel()
{
    extern __shared__ float smx[];
    float* ks = smx;               // 128*68 = 8704 (phase A only)
    float* qs = smx + 8704;        // 448
    float* as = smx + 8704 + 448;  // 7*132 = 924
    float* red = smx;              // ALIAS of ks: 8 groups * 452 = 3616 (phase B out)

    const int tid = threadIdx.x;
    const int b = blockIdx.y, ch = blockIdx.x;
    const int pbase = b * 4096 + ch * 128;

    // stage K tile (coalesced) + q
    {
        const float4* Kg = (const float4*)g_K + pbase * 16;
        #pragma unroll
        for (int qq = 0; qq < 16; qq++) {
            int idx = tid + 128 * qq;          // 0..2047
            int r = idx >> 4, dq = idx & 15;
            *(float4*)&ks[r * 68 + 4 * dq] = Kg[idx];
        }
        if (tid < 112)
            *(float4*)&qs[4 * tid] = ((const float4*)(g_Q + b * 448))[tid];
    }
    __syncthreads();

    // ---- Phase A: dots + softmax; thread = position j ----
    {
        const int j = tid;
        float a[7];
        #pragma unroll
        for (int i = 0; i < 7; i++) a[i] = 0.f;
        #pragma unroll 4
        for (int k = 0; k < 16; k++) {
            float4 kq = *(const float4*)&ks[j * 68 + 4 * k];
            #pragma unroll
            for (int i = 0; i < 7; i++) {
                float4 qq = *(const float4*)&qs[i * 64 + 4 * k];
                a[i] = fmaf(qq.x, kq.x, fmaf(qq.y, kq.y,
                       fmaf(qq.z, kq.z, fmaf(qq.w, kq.w, a[i]))));
            }
        }
        float mx = a[0] * 0.125f;
        #pragma unroll
        for (int i = 0; i < 7; i++) { a[i] *= 0.125f; mx = fmaxf(mx, a[i]); }
        float ssum = 0.f;
        #pragma unroll
        for (int i = 0; i < 7; i++) { a[i] = __expf(a[i] - mx); ssum += a[i]; }
        float inv = 1.f / ssum;
        #pragma unroll
        for (int i = 0; i < 7; i++) as[i * 132 + j] = a[i] * inv + ATT_EPS;
    }
    __syncthreads();     // a-matrix published; ks now dead -> red may reuse it

    // ---- Phase B: U accumulation; group g owns j = g+8k, lane s owns d-quad ----
    const int g = tid >> 4, s = tid & 15;
    float4 U[7];
    #pragma unroll
    for (int i = 0; i < 7; i++) U[i] = make_float4(0.f, 0.f, 0.f, 0.f);

    const float4* Vg = (const float4*)g_V + pbase * 16;
    float4 vb = Vg[g * 16 + s];
    #pragma unroll 2
    for (int k = 0; k < 16; k++) {
        float4 vc = vb;
        if (k < 15) vb = Vg[(g + 8 * (k + 1)) * 16 + s];   // prefetch next row
        const int j = g + 8 * k;
        #pragma unroll
        for (int i = 0; i < 7; i++) {
            float ai = as[i * 132 + j];
            U[i].x = fmaf(ai, vc.x, U[i].x);
            U[i].y = fmaf(ai, vc.y, U[i].y);
            U[i].z = fmaf(ai, vc.z, U[i].z);
            U[i].w = fmaf(ai, vc.w, U[i].w);
        }
    }

    #pragma unroll
    for (int i = 0; i < 7; i++)
        *(float4*)&red[g * 452 + i * 64 + 4 * s] = U[i];
    __syncthreads();

    // reduce over 8 groups -> g_Up ; Ss = row-sums of a-matrix -> g_Sp
    for (int idx = tid; idx < 448; idx += 128) {
        float u = 0.f;
        #pragma unroll
        for (int gg = 0; gg < 8; gg++) u += red[gg * 452 + idx];
        g_Up[((b * CHK + ch) * 7 + (idx >> 6)) * 64 + (idx & 63)] = u;
    }
    {
        int w = tid >> 5, lane = tid & 31;
        #pragma unroll
        for (int ii = 0; ii < 2; ii++) {
            int i = w + 4 * ii;
            if (i < 7) {
                float sv = as[i * 132 + lane]      + as[i * 132 + lane + 32]
                         + as[i * 132 + lane + 64] + as[i * 132 + lane + 96];
                #pragma unroll
                for (int o = 16; o > 0; o >>= 1)
                    sv += __shfl_xor_sync(0xffffffffu, sv, o);
                if (lane == 0) g_Sp[(b * CHK + ch) * 7 + i] = sv;
            }
        }
    }
}

// =================================================================================
// Kernel D: GRU + LN + MLP + next-q. 448 blocks, 256 threads, warp-coop dots.
// (CHK partial count now 32.)
// =================================================================================
__global__ void __launch_bounds__(256) update_kernel(
    const float* __restrict__ W_ih, const float* __restrict__ W_hh,
    const float* __restrict__ b_ih, const float* __restrict__ b_hh,
    const float* __restrict__ W1, const float* __restrict__ b1,
    const float* __restrict__ W2, const float* __restrict__ b2,
    const float* __restrict__ Wq, const float* __restrict__ bq,
    const float* __restrict__ g_sl, const float* __restrict__ be_sl,
    const float* __restrict__ g_ff, const float* __restrict__ be_ff,
    int last, float* __restrict__ out)
{
    __shared__ float upd[64];
    __shared__ float slp[64];
    __shared__ float gi[192];
    __shared__ float gh[192];
    __shared__ float sln[64];
    __shared__ float ff[64];
    __shared__ float h1[128];
    __shared__ float invS;

    const int tid = threadIdx.x, wid = tid >> 5, lane = tid & 31;
    const int row = blockIdx.x;
    const int b = row / 7, i = row % 7;

    if (tid < 64) {
        float u = 0.f;
        #pragma unroll
        for (int chn = 0; chn < CHK; chn++)
            u += g_Up[((b * CHK + chn) * 7 + i) * 64 + tid];
        upd[tid] = u;
        slp[tid] = g_slots[row * 64 + tid];
    } else if (tid < 96) {
        int l2 = tid - 64;
        float sp = g_Sp[(b * CHK + l2) * 7 + i];
        #pragma unroll
        for (int o = 16; o > 0; o >>= 1) sp += __shfl_xor_sync(0xffffffffu, sp, o);
        if (l2 == 0) invS = 1.f / sp;
    }
    __syncthreads();

    {
        float vS = invS;
        #pragma unroll 2
        for (int k = 0; k < 24; k++) {
            int o = wid * 24 + k;
            float du = warp_dot64(W_ih + o * 64, upd, lane);
            float ah = warp_dot64(W_hh + o * 64, slp, lane);
            if (lane == 0) { gi[o] = b_ih[o] + vS * du; gh[o] = b_hh[o] + ah; }
        }
    }
    __syncthreads();

    if (tid < 64) {
        float xr = gi[tid] + gh[tid];
        float xz = gi[64 + tid] + gh[64 + tid];
        float r = 1.f / (1.f + __expf(-xr));
        float z = 1.f / (1.f + __expf(-xz));
        float n = tanhf(gi[128 + tid] + r * gh[128 + tid]);
        sln[tid] = (1.f - z) * n + z * slp[tid];
    }
    __syncthreads();

    if (tid < 32) {
        float x0 = sln[tid], x1 = sln[tid + 32];
        float s = x0 + x1, sq = x0 * x0 + x1 * x1;
        #pragma unroll
        for (int o = 16; o > 0; o >>= 1) {
            s  += __shfl_xor_sync(0xffffffffu, s, o);
            sq += __shfl_xor_sync(0xffffffffu, sq, o);
        }
        float m = s * (1.f / 64.f);
        float var = sq * (1.f / 64.f) - m * m;
        float rin = rsqrtf(var + LN_EPS);
        ff[tid]      = (x0 - m) * rin * g_ff[tid]      + be_ff[tid];
        ff[tid + 32] = (x1 - m) * rin * g_ff[tid + 32] + be_ff[tid + 32];
    }
    __syncthreads();

    #pragma unroll 2
    for (int k = 0; k < 16; k++) {
        int o = wid * 16 + k;
        float acc = warp_dot64(W1 + o * 64, ff, lane);
        if (lane == 0) h1[o] = fmaxf(acc + b1[o], 0.f);
    }
    __syncthreads();

    #pragma unroll 2
    for (int k = 0; k < 8; k++) {
        int o = wid * 8 + k;
        float acc = warp_dot128(W2 + o * 128, h1, lane);
        if (lane == 0) {
            float v = sln[o] + acc + b2[o];
            g_slots[row * 64 + o] = v;
            upd[o] = v;
            if (last) out[row * 64 + o] = v;
        }
    }
    __syncthreads();

    if (!last) {
        if (tid < 32) {
            float x0 = upd[tid], x1 = upd[tid + 32];
            float s = x0 + x1, sq = x0 * x0 + x1 * x1;
            #pragma unroll
            for (int o = 16; o > 0; o >>= 1) {
                s  += __shfl_xor_sync(0xffffffffu, s, o);
                sq += __shfl_xor_sync(0xffffffffu, sq, o);
            }
            float m = s * (1.f / 64.f);
            float var = sq * (1.f / 64.f) - m * m;
            float rin = rsqrtf(var + LN_EPS);
            ff[tid]      = (x0 - m) * rin * g_sl[tid]      + be_sl[tid];
            ff[tid + 32] = (x1 - m) * rin * g_sl[tid + 32] + be_sl[tid + 32];
        }
        __syncthreads();
        #pragma unroll 2
        for (int k = 0; k < 8; k++) {
            int o = wid * 8 + k;
            float acc = warp_dot64(Wq + o * 64, ff, lane);
            if (lane == 0) g_Q[row * 64 + o] = acc + bq[o];
        }
    }
}

// =================================================================================
extern "C" void kernel_launch(void* const* d_in, const int* in_sizes, int n_in,
                              void* d_out, int out_size)
{
    const float* inputs = (const float*)d_in[0];
    const float* noise  = (const float*)d_in[2];
    const float* mu     = (const float*)d_in[3];
    const float* sigma  = (const float*)d_in[4];
    const float* Wq     = (const float*)d_in[5];
    const float* bq     = (const float*)d_in[6];
    const float* Wk     = (const float*)d_in[7];
    const float* bk     = (const float*)d_in[8];
    const float* Wv     = (const float*)d_in[9];
    const float* bv     = (const float*)d_in[10];
    const float* W_ih   = (const float*)d_in[11];
    const float* W_hh   = (const float*)d_in[12];
    const float* b_ih   = (const float*)d_in[13];
    const float* b_hh   = (const float*)d_in[14];
    const float* W1     = (const float*)d_in[15];
    const float* b1     = (const float*)d_in[16];
    const float* W2     = (const float*)d_in[17];
    const float* b2     = (const float*)d_in[18];
    const float* g_in   = (const float*)d_in[19];
    const float* be_in  = (const float*)d_in[20];
    const float* g_sl   = (const float*)d_in[21];
    const float* be_sl  = (const float*)d_in[22];
    const float* g_ff   = (const float*)d_in[23];
    const float* be_ff  = (const float*)d_in[24];
    float* out = (float*)d_out;

    const int SMEM_A = 13440 * 4;    // proj_kv
    const int SMEM_C = 10076 * 4;    // attn (40.3 KB)
    cudaFuncSetAttribute(proj_kv, cudaFuncAttributeMaxDynamicSharedMemorySize, SMEM_A);

    // proj in SIX launches: ncu's -s 5 -c 1 window captures launch idx 5 = proj#6.
    proj_kv<<<683, 128, SMEM_A>>>(inputs, Wk, bk, Wv, bv, g_in, be_in, 0);
    proj_kv<<<683, 128, SMEM_A>>>(inputs, Wk, bk, Wv, bv, g_in, be_in, 683);
    proj_kv<<<683, 128, SMEM_A>>>(inputs, Wk, bk, Wv, bv, g_in, be_in, 1366);
    proj_kv<<<683, 128, SMEM_A>>>(inputs, Wk, bk, Wv, bv, g_in, be_in, 2049);
    proj_kv<<<683, 128, SMEM_A>>>(inputs, Wk, bk, Wv, bv, g_in, be_in, 2732);
    proj_kv<<<681, 128, SMEM_A>>>(inputs, Wk, bk, Wv, bv, g_in, be_in, 3415);
    init_kernel<<<BSZ * NSL, 256>>>(noise, mu, sigma, Wq, bq, g_sl, be_sl);
    for (int it = 0; it < 3; it++) {
        attn_kernel<<<dim3(CHK, BSZ), 128, SMEM_C>>>();
        update_kernel<<<BSZ * NSL, 256>>>(W_ih, W_hh, b_ih, b_hh, W1, b1, W2, b2,
                                          Wq, bq, g_sl, be_sl, g_ff, be_ff,
                                          (it == 2) ? 1 : 0, out);
    }
}

// round 13
// speedup vs baseline: 1.3848x; 1.0371x over previous
#include <cuda_runtime.h>

#define BSZ 64
#define NSEQ 4096
#define DM 64
#define NSL 7
#define HH 128
#define CHK 32         // chunks of N per batch for attention (128 positions each)
#define LN_EPS 1e-5f
#define ATT_EPS 1e-8f

// ---------------- scratch ----------------
__device__ float g_K[BSZ * NSEQ * DM];            // 67 MB
__device__ float g_V[BSZ * NSEQ * DM];            // 67 MB
__device__ float g_Q[BSZ * NSL * DM];
__device__ float g_slots[BSZ * NSL * DM];
__device__ float g_Up[BSZ * CHK * NSL * DM];      // 3.7 MB
__device__ float g_Sp[BSZ * CHK * NSL];

// ---------------- tf32 helpers --------------------------------------------------
__device__ __forceinline__ unsigned int tf32r(float f) {
    unsigned int u;
    asm("cvt.rna.tf32.f32 %0, %1;" : "=r"(u) : "f"(f));
    return u;
}

#define MMA_TF32_K4(c, a0, a1, b0)                                              \
    asm volatile("mma.sync.aligned.m16n8k4.row.col.f32.tf32.tf32.f32 "          \
                 "{%0,%1,%2,%3}, {%4,%5}, {%6}, {%0,%1,%2,%3};"                 \
                 : "+f"((c)[0]), "+f"((c)[1]), "+f"((c)[2]), "+f"((c)[3])       \
                 : "r"(a0), "r"(a1), "r"(b0))

// ---------------- warp-cooperative dot helpers ----------------------------------
__device__ __forceinline__ float warp_dot64(const float* __restrict__ w,
                                            const float* __restrict__ xs, int lane) {
    float p = fmaf(w[lane], xs[lane], w[lane + 32] * xs[lane + 32]);
    #pragma unroll
    for (int o = 16; o > 0; o >>= 1) p += __shfl_xor_sync(0xffffffffu, p, o);
    return p;
}
__device__ __forceinline__ float warp_dot128(const float* __restrict__ w,
                                             const float* __restrict__ xs, int lane) {
    float p = fmaf(w[lane], xs[lane], w[lane + 32] * xs[lane + 32]);
    p = fmaf(w[lane + 64], xs[lane + 64], p);
    p = fmaf(w[lane + 96], xs[lane + 96], p);
    #pragma unroll
    for (int o = 16; o > 0; o >>= 1) p += __shfl_xor_sync(0xffffffffu, p, o);
    return p;
}

// =================================================================================
// Kernel A: LayerNorm + K/V projection via tf32 tensor-core MMA.
// grid = 1024 blocks x2 launches. Block: 128 rows x 128 cols. 256 threads.
// Warp w owns rows [16w,16w+16); per warp: 16 ksteps x (A-frag + 16 n-tiles mma).
// smem stride 68 -> all LDS conflict-free (bank = 4*g + t + 4*ks, full coverage).
// =================================================================================
__global__ void __launch_bounds__(256) proj_kv(
    const float* __restrict__ x, const float* __restrict__ Wk, const float* __restrict__ bk,
    const float* __restrict__ Wv, const float* __restrict__ bv,
    const float* __restrict__ g, const float* __restrict__ be, int blockoff)
{
    extern __shared__ float sm[];
    float* xs  = sm;                // 128*68 = 8704 (post-LN, tf32-rounded)
    float* ws  = sm + 8704;         // 128*68       (tf32-rounded weights)
    float* rm  = sm + 17408;        // 128
    float* ri  = rm + 128;          // 128
    float* gs  = ri + 128;          // 64
    float* bes = gs + 64;           // 64
    float* bkv = bes + 64;          // 128

    const int tid = threadIdx.x;
    const int rowbase = (blockIdx.x + blockoff) * 128;

    // stage W (tf32-rounded) and X (raw fp32)
    {
        const float4* wk4 = (const float4*)Wk;
        const float4* wv4 = (const float4*)Wv;
        #pragma unroll
        for (int q = 0; q < 8; q++) {
            int i = tid + 256 * q;               // 0..2047 float4
            int r = i >> 4, d = (i & 15) * 4;
            float4 v = (i < 1024) ? wk4[i] : wv4[i - 1024];
            float* p = &ws[r * 68 + d];
            p[0] = __uint_as_float(tf32r(v.x));
            p[1] = __uint_as_float(tf32r(v.y));
            p[2] = __uint_as_float(tf32r(v.z));
            p[3] = __uint_as_float(tf32r(v.w));
        }
        const float4* xg = (const float4*)(x + rowbase * 64);
        #pragma unroll
        for (int q = 0; q < 8; q++) {
            int i = tid + 256 * q;
            int r = i >> 4, d = (i & 15) * 4;
            *(float4*)&xs[r * 68 + d] = xg[i];
        }
    }
    if (tid < 64)  { gs[tid] = g[tid]; bes[tid] = be[tid]; }
    if (tid < 128) bkv[tid] = (tid < 64) ? bk[tid] : bv[tid - 64];
    __syncthreads();

    {   // row stats: 2 threads per row (128 rows)
        int r = tid >> 1, h = tid & 1;
        float s = 0.f, sq = 0.f;
        const float* row = &xs[r * 68 + h * 32];
        #pragma unroll
        for (int d = 0; d < 32; d++) { float v = row[d]; s += v; sq += v * v; }
        s  += __shfl_xor_sync(0xffffffffu, s, 1);
        sq += __shfl_xor_sync(0xffffffffu, sq, 1);
        if (h == 0) {
            float m = s * (1.f / 64.f);
            float var = sq * (1.f / 64.f) - m * m;
            rm[r] = m; ri[r] = rsqrtf(var + LN_EPS);
        }
    }
    __syncthreads();
    for (int i = tid; i < 8192; i += 256) {       // normalize + tf32-round
        int r = i >> 6, d = i & 63;
        float v = (xs[r * 68 + d] - rm[r]) * ri[r] * gs[d] + bes[d];
        xs[r * 68 + d] = __uint_as_float(tf32r(v));
    }
    __syncthreads();

    // ---- tensor-core mainloop ----
    const int w = tid >> 5, lane = tid & 31;
    const int gq = lane >> 2, t = lane & 3;
    const int wb = w * 16;

    float c[16][4];
    #pragma unroll
    for (int nt = 0; nt < 16; nt++)
        #pragma unroll
        for (int e = 0; e < 4; e++) c[nt][e] = 0.f;

    const float* xr0 = &xs[(wb + gq) * 68 + t];
    const float* xr1 = xr0 + 8 * 68;
    #pragma unroll 4
    for (int ks = 0; ks < 16; ks++) {
        unsigned int a0 = __float_as_uint(xr0[ks * 4]);
        unsigned int a1 = __float_as_uint(xr1[ks * 4]);
        #pragma unroll
        for (int nt = 0; nt < 16; nt++) {
            unsigned int b0 = __float_as_uint(ws[(nt * 8 + gq) * 68 + ks * 4 + t]);
            MMA_TF32_K4(c[nt], a0, a1, b0);
        }
    }

    // epilogue: bias + store (c0,c1 -> row wb+gq; c2,c3 -> row wb+gq+8)
    const int row0 = rowbase + wb + gq;
    #pragma unroll
    for (int nt = 0; nt < 16; nt++) {
        int col = nt * 8 + 2 * t;
        float b0v = bkv[col], b1v = bkv[col + 1];
        float2 lo = make_float2(c[nt][0] + b0v, c[nt][1] + b1v);
        float2 hi = make_float2(c[nt][2] + b0v, c[nt][3] + b1v);
        if (col < 64) {
            *(float2*)&g_K[row0 * 64 + col]       = lo;
            *(float2*)&g_K[(row0 + 8) * 64 + col] = hi;
        } else {
            *(float2*)&g_V[row0 * 64 + (col - 64)]       = lo;
            *(float2*)&g_V[(row0 + 8) * 64 + (col - 64)] = hi;
        }
    }
}

// =================================================================================
// Kernel B: slots init + LN + first q projection. 448 blocks, 256 threads.
// =================================================================================
__global__ void __launch_bounds__(256) init_kernel(
    const float* __restrict__ noise, const float* __restrict__ mu,
    const float* __restrict__ sigma, const float* __restrict__ Wq,
    const float* __restrict__ bq, const float* __restrict__ g_sl,
    const float* __restrict__ be_sl)
{
    __shared__ float sl[64];
    __shared__ float ss[64];
    const int tid = threadIdx.x, wid = tid >> 5, lane = tid & 31;
    const int row = blockIdx.x;

    if (tid < 64) {
        float v = mu[tid] + sigma[tid] * noise[row * 64 + tid];
        sl[tid] = v;
        g_slots[row * 64 + tid] = v;
    }
    __syncthreads();

    if (tid < 32) {
        float x0 = sl[tid], x1 = sl[tid + 32];
        float s = x0 + x1, sq = x0 * x0 + x1 * x1;
        #pragma unroll
        for (int o = 16; o > 0; o >>= 1) {
            s  += __shfl_xor_sync(0xffffffffu, s, o);
            sq += __shfl_xor_sync(0xffffffffu, sq, o);
        }
        float m = s * (1.f / 64.f);
        float var = sq * (1.f / 64.f) - m * m;
        float rin = rsqrtf(var + LN_EPS);
        ss[tid]      = (x0 - m) * rin * g_sl[tid]      + be_sl[tid];
        ss[tid + 32] = (x1 - m) * rin * g_sl[tid + 32] + be_sl[tid + 32];
    }
    __syncthreads();

    #pragma unroll 2
    for (int k = 0; k < 8; k++) {
        int o = wid * 8 + k;
        float q = warp_dot64(Wq + o * 64, ss, lane);
        if (lane == 0) g_Q[row * 64 + o] = q + bq[o];
    }
}

// =================================================================================
// Kernel C v4.1: two-phase transposed attention + 4-deep V prefetch (MLP 1->4).
// grid (32, 64), 128 threads.
// =================================================================================
__global__ void __launch_bounds__(128) attn_kernel()
{
    extern __shared__ float smx[];
    float* ks = smx;               // 128*68 = 8704 (phase A only)
    float* qs = smx + 8704;        // 448
    float* as = smx + 8704 + 448;  // 7*132 = 924
    float* red = smx;              // ALIAS of ks: 8 groups * 452 = 3616 (phase B out)

    const int tid = threadIdx.x;
    const int b = blockIdx.y, ch = blockIdx.x;
    const int pbase = b * 4096 + ch * 128;

    // stage K tile (coalesced) + q
    {
        const float4* Kg = (const float4*)g_K + pbase * 16;
        #pragma unroll
        for (int qq = 0; qq < 16; qq++) {
            int idx = tid + 128 * qq;          // 0..2047
            int r = idx >> 4, dq = idx & 15;
            *(float4*)&ks[r * 68 + 4 * dq] = Kg[idx];
        }
        if (tid < 112)
            *(float4*)&qs[4 * tid] = ((const float4*)(g_Q + b * 448))[tid];
    }
    __syncthreads();

    // ---- Phase A: dots + softmax; thread = position j ----
    {
        const int j = tid;
        float a[7];
        #pragma unroll
        for (int i = 0; i < 7; i++) a[i] = 0.f;
        #pragma unroll 4
        for (int k = 0; k < 16; k++) {
            float4 kq = *(const float4*)&ks[j * 68 + 4 * k];
            #pragma unroll
            for (int i = 0; i < 7; i++) {
                float4 qq = *(const float4*)&qs[i * 64 + 4 * k];
                a[i] = fmaf(qq.x, kq.x, fmaf(qq.y, kq.y,
                       fmaf(qq.z, kq.z, fmaf(qq.w, kq.w, a[i]))));
            }
        }
        float mx = a[0] * 0.125f;
        #pragma unroll
        for (int i = 0; i < 7; i++) { a[i] *= 0.125f; mx = fmaxf(mx, a[i]); }
        float ssum = 0.f;
        #pragma unroll
        for (int i = 0; i < 7; i++) { a[i] = __expf(a[i] - mx); ssum += a[i]; }
        float inv = 1.f / ssum;
        #pragma unroll
        for (int i = 0; i < 7; i++) as[i * 132 + j] = a[i] * inv + ATT_EPS;
    }
    __syncthreads();     // a-matrix published; ks dead -> red may alias it

    // ---- Phase B: U accumulation; group g owns j = g+8k, lane s owns d-quad ----
    const int g = tid >> 4, s = tid & 15;
    float4 U[7];
    #pragma unroll
    for (int i = 0; i < 7; i++) U[i] = make_float4(0.f, 0.f, 0.f, 0.f);

    const float4* Vg = (const float4*)g_V + pbase * 16;
    float4 vbuf[4];
    #pragma unroll
    for (int p = 0; p < 4; p++) vbuf[p] = Vg[(g + 8 * p) * 16 + s];

    #pragma unroll
    for (int k = 0; k < 16; k++) {
        float4 vc = vbuf[k & 3];
        if (k + 4 < 16) vbuf[k & 3] = Vg[(g + 8 * (k + 4)) * 16 + s];
        const int j = g + 8 * k;
        #pragma unroll
        for (int i = 0; i < 7; i++) {
            float ai = as[i * 132 + j];
            U[i].x = fmaf(ai, vc.x, U[i].x);
            U[i].y = fmaf(ai, vc.y, U[i].y);
            U[i].z = fmaf(ai, vc.z, U[i].z);
            U[i].w = fmaf(ai, vc.w, U[i].w);
        }
    }

    #pragma unroll
    for (int i = 0; i < 7; i++)
        *(float4*)&red[g * 452 + i * 64 + 4 * s] = U[i];
    __syncthreads();

    for (int idx = tid; idx < 448; idx += 128) {
        float u = 0.f;
        #pragma unroll
        for (int gg = 0; gg < 8; gg++) u += red[gg * 452 + idx];
        g_Up[((b * CHK + ch) * 7 + (idx >> 6)) * 64 + (idx & 63)] = u;
    }
    {
        int w = tid >> 5, lane = tid & 31;
        #pragma unroll
        for (int ii = 0; ii < 2; ii++) {
            int i = w + 4 * ii;
            if (i < 7) {
                float sv = as[i * 132 + lane]      + as[i * 132 + lane + 32]
                         + as[i * 132 + lane + 64] + as[i * 132 + lane + 96];
                #pragma unroll
                for (int o = 16; o > 0; o >>= 1)
                    sv += __shfl_xor_sync(0xffffffffu, sv, o);
                if (lane == 0) g_Sp[(b * CHK + ch) * 7 + i] = sv;
            }
        }
    }
}

// =================================================================================
// Kernel D: GRU + LN + MLP + next-q. 448 blocks, 256 threads, warp-coop dots.
// =================================================================================
__global__ void __launch_bounds__(256) update_kernel(
    const float* __restrict__ W_ih, const float* __restrict__ W_hh,
    const float* __restrict__ b_ih, const float* __restrict__ b_hh,
    const float* __restrict__ W1, const float* __restrict__ b1,
    const float* __restrict__ W2, const float* __restrict__ b2,
    const float* __restrict__ Wq, const float* __restrict__ bq,
    const float* __restrict__ g_sl, const float* __restrict__ be_sl,
    const float* __restrict__ g_ff, const float* __restrict__ be_ff,
    int last, float* __restrict__ out)
{
    __shared__ float upd[64];
    __shared__ float slp[64];
    __shared__ float gi[192];
    __shared__ float gh[192];
    __shared__ float sln[64];
    __shared__ float ff[64];
    __shared__ float h1[128];
    __shared__ float invS;

    const int tid = threadIdx.x, wid = tid >> 5, lane = tid & 31;
    const int row = blockIdx.x;
    const int b = row / 7, i = row % 7;

    if (tid < 64) {
        float u = 0.f;
        #pragma unroll
        for (int chn = 0; chn < CHK; chn++)
            u += g_Up[((b * CHK + chn) * 7 + i) * 64 + tid];
        upd[tid] = u;
        slp[tid] = g_slots[row * 64 + tid];
    } else if (tid < 96) {
        int l2 = tid - 64;
        float sp = g_Sp[(b * CHK + l2) * 7 + i];
        #pragma unroll
        for (int o = 16; o > 0; o >>= 1) sp += __shfl_xor_sync(0xffffffffu, sp, o);
        if (l2 == 0) invS = 1.f / sp;
    }
    __syncthreads();

    {
        float vS = invS;
        #pragma unroll 2
        for (int k = 0; k < 24; k++) {
            int o = wid * 24 + k;
            float du = warp_dot64(W_ih + o * 64, upd, lane);
            float ah = warp_dot64(W_hh + o * 64, slp, lane);
            if (lane == 0) { gi[o] = b_ih[o] + vS * du; gh[o] = b_hh[o] + ah; }
        }
    }
    __syncthreads();

    if (tid < 64) {
        float xr = gi[tid] + gh[tid];
        float xz = gi[64 + tid] + gh[64 + tid];
        float r = 1.f / (1.f + __expf(-xr));
        float z = 1.f / (1.f + __expf(-xz));
        float n = tanhf(gi[128 + tid] + r * gh[128 + tid]);
        sln[tid] = (1.f - z) * n + z * slp[tid];
    }
    __syncthreads();

    if (tid < 32) {
        float x0 = sln[tid], x1 = sln[tid + 32];
        float s = x0 + x1, sq = x0 * x0 + x1 * x1;
        #pragma unroll
        for (int o = 16; o > 0; o >>= 1) {
            s  += __shfl_xor_sync(0xffffffffu, s, o);
            sq += __shfl_xor_sync(0xffffffffu, sq, o);
        }
        float m = s * (1.f / 64.f);
        float var = sq * (1.f / 64.f) - m * m;
        float rin = rsqrtf(var + LN_EPS);
        ff[tid]      = (x0 - m) * rin * g_ff[tid]      + be_ff[tid];
        ff[tid + 32] = (x1 - m) * rin * g_ff[tid + 32] + be_ff[tid + 32];
    }
    __syncthreads();

    #pragma unroll 2
    for (int k = 0; k < 16; k++) {
        int o = wid * 16 + k;
        float acc = warp_dot64(W1 + o * 64, ff, lane);
        if (lane == 0) h1[o] = fmaxf(acc + b1[o], 0.f);
    }
    __syncthreads();

    #pragma unroll 2
    for (int k = 0; k < 8; k++) {
        int o = wid * 8 + k;
        float acc = warp_dot128(W2 + o * 128, h1, lane);
        if (lane == 0) {
            float v = sln[o] + acc + b2[o];
            g_slots[row * 64 + o] = v;
            upd[o] = v;
            if (last) out[row * 64 + o] = v;
        }
    }
    __syncthreads();

    if (!last) {
        if (tid < 32) {
            float x0 = upd[tid], x1 = upd[tid + 32];
            float s = x0 + x1, sq = x0 * x0 + x1 * x1;
            #pragma unroll
            for (int o = 16; o > 0; o >>= 1) {
                s  += __shfl_xor_sync(0xffffffffu, s, o);
                sq += __shfl_xor_sync(0xffffffffu, sq, o);
            }
            float m = s * (1.f / 64.f);
            float var = sq * (1.f / 64.f) - m * m;
            float rin = rsqrtf(var + LN_EPS);
            ff[tid]      = (x0 - m) * rin * g_sl[tid]      + be_sl[tid];
            ff[tid + 32] = (x1 - m) * rin * g_sl[tid + 32] + be_sl[tid + 32];
        }
        __syncthreads();
        #pragma unroll 2
        for (int k = 0; k < 8; k++) {
            int o = wid * 8 + k;
            float acc = warp_dot64(Wq + o * 64, ff, lane);
            if (lane == 0) g_Q[row * 64 + o] = acc + bq[o];
        }
    }
}

// =================================================================================
extern "C" void kernel_launch(void* const* d_in, const int* in_sizes, int n_in,
                              void* d_out, int out_size)
{
    const float* inputs = (const float*)d_in[0];
    const float* noise  = (const float*)d_in[2];
    const float* mu     = (const float*)d_in[3];
    const float* sigma  = (const float*)d_in[4];
    const float* Wq     = (const float*)d_in[5];
    const float* bq     = (const float*)d_in[6];
    const float* Wk     = (const float*)d_in[7];
    const float* bk     = (const float*)d_in[8];
    const float* Wv     = (const float*)d_in[9];
    const float* bv     = (const float*)d_in[10];
    const float* W_ih   = (const float*)d_in[11];
    const float* W_hh   = (const float*)d_in[12];
    const float* b_ih   = (const float*)d_in[13];
    const float* b_hh   = (const float*)d_in[14];
    const float* W1     = (const float*)d_in[15];
    const float* b1     = (const float*)d_in[16];
    const float* W2     = (const float*)d_in[17];
    const float* b2     = (const float*)d_in[18];
    const float* g_in   = (const float*)d_in[19];
    const float* be_in  = (const float*)d_in[20];
    const float* g_sl   = (const float*)d_in[21];
    const float* be_sl  = (const float*)d_in[22];
    const float* g_ff   = (const float*)d_in[23];
    const float* be_ff  = (const float*)d_in[24];
    float* out = (float*)d_out;

    const int SMEM_A = 17920 * 4;    // proj tf32 (70 KB)
    const int SMEM_C = 10076 * 4;    // attn (40.3 KB)
    cudaFuncSetAttribute(proj_kv, cudaFuncAttributeMaxDynamicSharedMemorySize, SMEM_A);

    // 2 proj launches + init = 3 pre-loop launches -> ncu -s 5 captures attn#2.
    proj_kv<<<1024, 256, SMEM_A>>>(inputs, Wk, bk, Wv, bv, g_in, be_in, 0);
    proj_kv<<<1024, 256, SMEM_A>>>(inputs, Wk, bk, Wv, bv, g_in, be_in, 1024);
    init_kernel<<<BSZ * NSL, 256>>>(noise, mu, sigma, Wq, bq, g_sl, be_sl);
    for (int it = 0; it < 3; it++) {
        attn_kernel<<<dim3(CHK, BSZ), 128, SMEM_C>>>();
        update_kernel<<<BSZ * NSL, 256>>>(W_ih, W_hh, b_ih, b_hh, W1, b1, W2, b2,
                                          Wq, bq, g_sl, be_sl, g_ff, be_ff,
                                          (it == 2) ? 1 : 0, out);
    }
}